// round 15
// baseline (speedup 1.0000x reference)
#include <cuda_runtime.h>
#include <math.h>

#define DIMC 512
#define HC   1024
#define BC   64
#define VC   64
#define JT   4
#define PRE_N (3 * BC * HC)

__device__ __align__(16) float g_pre[PRE_N];
__device__ __align__(16) float g_pre2[2][PRE_N];   // K-half partials

__device__ __forceinline__ float ex2_approx(float x) {
    float y; asm("ex2.approx.f32 %0, %1;" : "=f"(y) : "f"(x)); return y;
}
__device__ __forceinline__ float rcp_approx(float x) {
    float y; asm("rcp.approx.f32 %0, %1;" : "=f"(y) : "f"(x)); return y;
}
__device__ __forceinline__ float tanh_approx(float x) {
    float y; asm("tanh.approx.f32 %0, %1;" : "=f"(y) : "f"(x)); return y;
}
__device__ __forceinline__ unsigned long long pk2(float lo, float hi) {
    unsigned long long r; asm("mov.b64 %0, {%1,%2};" : "=l"(r) : "f"(lo), "f"(hi)); return r;
}
__device__ __forceinline__ void upk2(unsigned long long v, float& lo, float& hi) {
    asm("mov.b64 {%0,%1}, %2;" : "=f"(lo), "=f"(hi) : "l"(v));
}
__device__ __forceinline__ unsigned long long add2(unsigned long long a, unsigned long long b) {
    unsigned long long r; asm("add.rn.f32x2 %0, %1, %2;" : "=l"(r) : "l"(a), "l"(b)); return r;
}
__device__ __forceinline__ unsigned long long mul2(unsigned long long a, unsigned long long b) {
    unsigned long long r; asm("mul.rn.f32x2 %0, %1, %2;" : "=l"(r) : "l"(a), "l"(b)); return r;
}
__device__ __forceinline__ unsigned long long fma2(unsigned long long a, unsigned long long b, unsigned long long c) {
    unsigned long long r; asm("fma.rn.f32x2 %0, %1, %2, %3;" : "=l"(r) : "l"(a), "l"(b), "l"(c)); return r;
}

// Hendrycks tanh-form GELU: gelu(t) = 0.5*t*(1 + tanh(t*(C1 + C3*t^2)))
#define C1F (0.7978845608f)
#define C3F (0.0356774081f)

// one packed pair of evals accumulated into accr
#define GELU_ACC(xp, cp, wp, accr) do {                                  \
    unsigned long long t2 = add2((xp), (cp));                            \
    unsigned long long s2 = mul2(t2, t2);                                \
    unsigned long long q2 = fma2(s2, C3p, C1p);                          \
    unsigned long long u2 = mul2(q2, t2);                                \
    float ul, uh; upk2(u2, ul, uh);                                      \
    float thl = tanh_approx(ul);                                         \
    float thh = tanh_approx(uh);                                         \
    unsigned long long th2 = pk2(thl, thh);                              \
    unsigned long long hx2 = mul2(t2, H2p);                              \
    unsigned long long g2  = fma2(hx2, th2, hx2);                        \
    (accr) = fma2((wp), g2, (accr));                                     \
} while (0)

// ---------------------------------------------------------------------------
// Kernel 1: pre-activation K-half partials, direct store (no atomics/memset).
// grid = 3m x 32ct x 4rt x 2ks = 768 blocks, 128 thr.
// ---------------------------------------------------------------------------
__global__ __launch_bounds__(128) void gemm_pre_kernel(
        const float* __restrict__ state, const float* __restrict__ action,
        const float* __restrict__ embed, const float* __restrict__ W1) {
    const int ks  = blockIdx.x & 1;
    const int rt  = (blockIdx.x >> 1) & 3;
    const int b2i = blockIdx.x >> 3;          // 0..95
    const int m   = b2i >> 5;                 // 0..2
    const int ct  = b2i & 31;                 // cols ct*32
    const int tid = threadIdx.x;              // 128

    __shared__ float As[16][33];
    __shared__ __align__(16) float Ws[32][36];

    const int r  = tid & 15;
    const int cg = tid >> 4;                  // 0..7 -> cols cg*4..+4

    const int rbase = rt * 16;
    const int kbase = ks * 256;
    const int cbase = ct * 32;

    float acc[4] = {0.f, 0.f, 0.f, 0.f};

    const float* Wbase = W1 + (size_t)(m * DIMC + kbase) * HC + cbase;

    float a_pref[4];
    float w_pref[8];

#pragma unroll
    for (int i = 0; i < 4; ++i) {
        int idx = tid + i * 128;
        int rr = idx >> 5, kk = idx & 31;
        int grow = rbase + rr, gk = kbase + kk;
        if (m == 2) a_pref[i] = state[grow * DIMC + gk] + action[grow * DIMC + gk];
        else        a_pref[i] = embed[grow * DIMC + gk];
    }
#pragma unroll
    for (int i = 0; i < 8; ++i) {
        int idx = tid + i * 128;
        int kk = idx >> 5, cc = idx & 31;
        w_pref[i] = Wbase[(size_t)kk * HC + cc];
    }

    for (int ch = 0; ch < 8; ++ch) {
        __syncthreads();
#pragma unroll
        for (int i = 0; i < 4; ++i) {
            int idx = tid + i * 128;
            As[idx >> 5][idx & 31] = a_pref[i];
        }
#pragma unroll
        for (int i = 0; i < 8; ++i) {
            int idx = tid + i * 128;
            Ws[idx >> 5][idx & 31] = w_pref[i];
        }
        __syncthreads();

        if (ch < 7) {
            const int k0 = kbase + (ch + 1) * 32;
#pragma unroll
            for (int i = 0; i < 4; ++i) {
                int idx = tid + i * 128;
                int rr = idx >> 5, kk = idx & 31;
                int grow = rbase + rr, gk = k0 + kk;
                if (m == 2) a_pref[i] = state[grow * DIMC + gk] + action[grow * DIMC + gk];
                else        a_pref[i] = embed[grow * DIMC + gk];
            }
#pragma unroll
            for (int i = 0; i < 8; ++i) {
                int idx = tid + i * 128;
                int kk = idx >> 5, cc = idx & 31;
                w_pref[i] = Wbase[(size_t)((ch + 1) * 32 + kk) * HC + cc];
            }
        }

#pragma unroll
        for (int k = 0; k < 32; ++k) {
            float a = As[r][k];
            float4 w4 = *reinterpret_cast<const float4*>(&Ws[k][cg * 4]);
            acc[0] = fmaf(a, w4.x, acc[0]);
            acc[1] = fmaf(a, w4.y, acc[1]);
            acc[2] = fmaf(a, w4.z, acc[2]);
            acc[3] = fmaf(a, w4.w, acc[3]);
        }
    }

    float* out = g_pre2[ks] + (size_t)(m * BC + rbase + r) * HC + cbase + cg * 4;
    *reinterpret_cast<float4*>(out) = make_float4(acc[0], acc[1], acc[2], acc[3]);
}

// ---------------------------------------------------------------------------
// Kernel 1b: reduce the two K-half partials (fixed order -> deterministic).
// 49152 float4; grid 96 x 512.
// ---------------------------------------------------------------------------
__global__ __launch_bounds__(512) void reduce_pre_kernel() {
    int idx = blockIdx.x * 512 + threadIdx.x;      // 0..49151
    const float4* p0 = reinterpret_cast<const float4*>(g_pre2[0]);
    const float4* p1 = reinterpret_cast<const float4*>(g_pre2[1]);
    float4 a = p0[idx], b = p1[idx];
    float4 r;
    r.x = a.x + b.x;
    r.y = a.y + b.y;
    r.z = a.z + b.z;
    r.w = a.w + b.w;
    reinterpret_cast<float4*>(g_pre)[idx] = r;
}

// ---------------------------------------------------------------------------
// Kernel 2: scores (round-13 proven config, untouched inner loop).
// grid = 64*16 = 1024 (i, jt). 256 thr = 8 warps, warp-per-b over 8 b-iters.
// ---------------------------------------------------------------------------
__global__ __launch_bounds__(256, 5) void score_kernel(
        const float* __restrict__ b1, const float* __restrict__ W2,
        const float* __restrict__ b2, float* __restrict__ out) {
    const int i  = blockIdx.x >> 4;
    const int jt = blockIdx.x & 15;

    __shared__ __align__(16) float ce_s[JT][HC];
    __shared__ __align__(16) float w2s[HC];
    __shared__ float red[8][JT];

    const int tid  = threadIdx.x;
    const int warp = tid >> 5;
    const int lane = tid & 31;

    const float* cause  = g_pre;
    const float* effect = g_pre + BC * HC;
    const float* ctx    = g_pre + 2 * BC * HC;

    if (tid < 32) red[tid >> 2][tid & 3] = 0.0f;

    {
        const float4* c4 = reinterpret_cast<const float4*>(cause + i * HC);
        const float4* b4 = reinterpret_cast<const float4*>(b1);
        for (int t = tid; t < JT * HC / 4; t += 256) {
            int j = t >> 8, v = t & 255;
            float4 e4 = reinterpret_cast<const float4*>(effect + (jt * JT + j) * HC)[v];
            float4 cc = c4[v], bb = b4[v];
            float4 rr;
            rr.x = cc.x + e4.x + bb.x;
            rr.y = cc.y + e4.y + bb.y;
            rr.z = cc.z + e4.z + bb.z;
            rr.w = cc.w + e4.w + bb.w;
            reinterpret_cast<float4*>(ce_s[j])[v] = rr;
        }
        for (int t = tid; t < HC / 4; t += 256)
            reinterpret_cast<float4*>(w2s)[t] = reinterpret_cast<const float4*>(W2)[t];
    }
    __syncthreads();

    const unsigned long long C1p = pk2(C1F, C1F);
    const unsigned long long C3p = pk2(C3F, C3F);
    const unsigned long long H2p = pk2(0.5f, 0.5f);
    const float bias2 = b2[0];

    for (int bi = 0; bi < 8; ++bi) {
        const int b = bi * 8 + warp;
        const ulonglong2* ctx2 = reinterpret_cast<const ulonglong2*>(ctx + (size_t)b * HC);
        const ulonglong2* w22  = reinterpret_cast<const ulonglong2*>(w2s);

        unsigned long long acc2[JT];
#pragma unroll
        for (int j = 0; j < JT; ++j) acc2[j] = 0ull;

#pragma unroll 2
        for (int v = lane; v < HC / 4; v += 32) {
            const ulonglong2 x2 = ctx2[v];
            const ulonglong2 wv = w22[v];
#pragma unroll
            for (int j = 0; j < JT; ++j) {
                const ulonglong2 c2 = reinterpret_cast<const ulonglong2*>(ce_s[j])[v];
                GELU_ACC(x2.x, c2.x, wv.x, acc2[j]);
                GELU_ACC(x2.y, c2.y, wv.y, acc2[j]);
            }
        }

        float acc[JT];
#pragma unroll
        for (int j = 0; j < JT; ++j) {
            float lo, hi; upk2(acc2[j], lo, hi);
            acc[j] = lo + hi;
        }
#pragma unroll
        for (int off = 16; off; off >>= 1)
#pragma unroll
            for (int j = 0; j < JT; ++j)
                acc[j] += __shfl_xor_sync(0xffffffffu, acc[j], off);

        if (lane == 0) {
#pragma unroll
            for (int j = 0; j < JT; ++j) {
                float logit = acc[j] + bias2;
                float en = ex2_approx(-1.44269504f * logit);
                red[warp][j] += rcp_approx(1.0f + en);
            }
        }
    }

    __syncthreads();
    if (tid < JT) {
        float s = 0.0f;
#pragma unroll
        for (int w = 0; w < 8; ++w) s += red[w][tid];
        out[i * VC + jt * JT + tid] = s * (1.0f / BC);
    }
}

// ---------------------------------------------------------------------------
extern "C" void kernel_launch(void* const* d_in, const int* in_sizes, int n_in,
                              void* d_out, int out_size) {
    const float* state  = (const float*)d_in[0];
    const float* action = (const float*)d_in[1];
    const float* embed  = (const float*)d_in[2];
    const float* W1     = (const float*)d_in[3];
    const float* b1     = (const float*)d_in[4];
    const float* W2     = (const float*)d_in[5];
    const float* b2     = (const float*)d_in[6];
    float* out          = (float*)d_out;

    gemm_pre_kernel<<<3 * 32 * 4 * 2, 128>>>(state, action, embed, W1);
    reduce_pre_kernel<<<96, 512>>>();
    score_kernel<<<VC * 16, 256>>>(b1, W2, b2, out);
}

// round 16
// speedup vs baseline: 1.0063x; 1.0063x over previous
#include <cuda_runtime.h>
#include <math.h>

#define DIMC 512
#define HC   1024
#define BC   64
#define VC   64
#define JT   4
#define KSPLIT 4
#define PRE_N (3 * BC * HC)

__device__ __align__(16) float g_pre[PRE_N];
__device__ __align__(16) float g_pre4[KSPLIT][PRE_N];   // K-quarter partials

__device__ __forceinline__ float ex2_approx(float x) {
    float y; asm("ex2.approx.f32 %0, %1;" : "=f"(y) : "f"(x)); return y;
}
__device__ __forceinline__ float rcp_approx(float x) {
    float y; asm("rcp.approx.f32 %0, %1;" : "=f"(y) : "f"(x)); return y;
}
__device__ __forceinline__ float tanh_approx(float x) {
    float y; asm("tanh.approx.f32 %0, %1;" : "=f"(y) : "f"(x)); return y;
}
__device__ __forceinline__ unsigned long long pk2(float lo, float hi) {
    unsigned long long r; asm("mov.b64 %0, {%1,%2};" : "=l"(r) : "f"(lo), "f"(hi)); return r;
}
__device__ __forceinline__ void upk2(unsigned long long v, float& lo, float& hi) {
    asm("mov.b64 {%0,%1}, %2;" : "=f"(lo), "=f"(hi) : "l"(v));
}
__device__ __forceinline__ unsigned long long add2(unsigned long long a, unsigned long long b) {
    unsigned long long r; asm("add.rn.f32x2 %0, %1, %2;" : "=l"(r) : "l"(a), "l"(b)); return r;
}
__device__ __forceinline__ unsigned long long mul2(unsigned long long a, unsigned long long b) {
    unsigned long long r; asm("mul.rn.f32x2 %0, %1, %2;" : "=l"(r) : "l"(a), "l"(b)); return r;
}
__device__ __forceinline__ unsigned long long fma2(unsigned long long a, unsigned long long b, unsigned long long c) {
    unsigned long long r; asm("fma.rn.f32x2 %0, %1, %2, %3;" : "=l"(r) : "l"(a), "l"(b), "l"(c)); return r;
}

// Hendrycks tanh-form GELU: gelu(t) = 0.5*t*(1 + tanh(t*(C1 + C3*t^2)))
#define C1F (0.7978845608f)
#define C3F (0.0356774081f)

// one packed pair of evals accumulated into accr
#define GELU_ACC(xp, cp, wp, accr) do {                                  \
    unsigned long long t2 = add2((xp), (cp));                            \
    unsigned long long s2 = mul2(t2, t2);                                \
    unsigned long long q2 = fma2(s2, C3p, C1p);                          \
    unsigned long long u2 = mul2(q2, t2);                                \
    float ul, uh; upk2(u2, ul, uh);                                      \
    float thl = tanh_approx(ul);                                         \
    float thh = tanh_approx(uh);                                         \
    unsigned long long th2 = pk2(thl, thh);                              \
    unsigned long long hx2 = mul2(t2, H2p);                              \
    unsigned long long g2  = fma2(hx2, th2, hx2);                        \
    (accr) = fma2((wp), g2, (accr));                                     \
} while (0)

// ---------------------------------------------------------------------------
// Kernel 1: pre-activation K-quarter partials, direct store (no atomics).
// grid = 3m x 32ct x 4rt x 4ks = 1536 blocks, 128 thr.
// Block = 16 rows x 32 cols x K=128, 4 double-buffered 32-k chunks.
// 197k total threads -> ~36 warps/SM for latency hiding.
// ---------------------------------------------------------------------------
__global__ __launch_bounds__(128) void gemm_pre_kernel(
        const float* __restrict__ state, const float* __restrict__ action,
        const float* __restrict__ embed, const float* __restrict__ W1) {
    const int ks  = blockIdx.x & 3;
    const int rt  = (blockIdx.x >> 2) & 3;
    const int b2i = blockIdx.x >> 4;          // 0..95
    const int m   = b2i >> 5;                 // 0..2
    const int ct  = b2i & 31;                 // cols ct*32
    const int tid = threadIdx.x;              // 128

    __shared__ float As[16][33];
    __shared__ __align__(16) float Ws[32][36];

    const int r  = tid & 15;
    const int cg = tid >> 4;                  // 0..7 -> cols cg*4..+4

    const int rbase = rt * 16;
    const int kbase = ks * 128;
    const int cbase = ct * 32;

    float acc[4] = {0.f, 0.f, 0.f, 0.f};

    const float* Wbase = W1 + (size_t)(m * DIMC + kbase) * HC + cbase;

    float a_pref[4];
    float w_pref[8];

#pragma unroll
    for (int i = 0; i < 4; ++i) {
        int idx = tid + i * 128;
        int rr = idx >> 5, kk = idx & 31;
        int grow = rbase + rr, gk = kbase + kk;
        if (m == 2) a_pref[i] = state[grow * DIMC + gk] + action[grow * DIMC + gk];
        else        a_pref[i] = embed[grow * DIMC + gk];
    }
#pragma unroll
    for (int i = 0; i < 8; ++i) {
        int idx = tid + i * 128;
        int kk = idx >> 5, cc = idx & 31;
        w_pref[i] = Wbase[(size_t)kk * HC + cc];
    }

    for (int ch = 0; ch < 4; ++ch) {          // 4 chunks of 32 k
        __syncthreads();
#pragma unroll
        for (int i = 0; i < 4; ++i) {
            int idx = tid + i * 128;
            As[idx >> 5][idx & 31] = a_pref[i];
        }
#pragma unroll
        for (int i = 0; i < 8; ++i) {
            int idx = tid + i * 128;
            Ws[idx >> 5][idx & 31] = w_pref[i];
        }
        __syncthreads();

        if (ch < 3) {
            const int k0 = kbase + (ch + 1) * 32;
#pragma unroll
            for (int i = 0; i < 4; ++i) {
                int idx = tid + i * 128;
                int rr = idx >> 5, kk = idx & 31;
                int grow = rbase + rr, gk = k0 + kk;
                if (m == 2) a_pref[i] = state[grow * DIMC + gk] + action[grow * DIMC + gk];
                else        a_pref[i] = embed[grow * DIMC + gk];
            }
#pragma unroll
            for (int i = 0; i < 8; ++i) {
                int idx = tid + i * 128;
                int kk = idx >> 5, cc = idx & 31;
                w_pref[i] = Wbase[(size_t)((ch + 1) * 32 + kk) * HC + cc];
            }
        }

#pragma unroll
        for (int k = 0; k < 32; ++k) {
            float a = As[r][k];
            float4 w4 = *reinterpret_cast<const float4*>(&Ws[k][cg * 4]);
            acc[0] = fmaf(a, w4.x, acc[0]);
            acc[1] = fmaf(a, w4.y, acc[1]);
            acc[2] = fmaf(a, w4.z, acc[2]);
            acc[3] = fmaf(a, w4.w, acc[3]);
        }
    }

    float* out = g_pre4[ks] + (size_t)(m * BC + rbase + r) * HC + cbase + cg * 4;
    *reinterpret_cast<float4*>(out) = make_float4(acc[0], acc[1], acc[2], acc[3]);
}

// ---------------------------------------------------------------------------
// Kernel 1b: reduce 4 K-quarter partials (fixed order -> deterministic).
// 49152 float4; grid 96 x 512.
// ---------------------------------------------------------------------------
__global__ __launch_bounds__(512) void reduce_pre_kernel() {
    int idx = blockIdx.x * 512 + threadIdx.x;      // 0..49151
    const float4* p0 = reinterpret_cast<const float4*>(g_pre4[0]);
    const float4* p1 = reinterpret_cast<const float4*>(g_pre4[1]);
    const float4* p2 = reinterpret_cast<const float4*>(g_pre4[2]);
    const float4* p3 = reinterpret_cast<const float4*>(g_pre4[3]);
    float4 a = p0[idx], b = p1[idx], c = p2[idx], d = p3[idx];
    float4 r;
    r.x = (a.x + b.x) + (c.x + d.x);
    r.y = (a.y + b.y) + (c.y + d.y);
    r.z = (a.z + b.z) + (c.z + d.z);
    r.w = (a.w + b.w) + (c.w + d.w);
    reinterpret_cast<float4*>(g_pre)[idx] = r;
}

// ---------------------------------------------------------------------------
// Kernel 2: scores (round-13 proven config, untouched).
// grid = 64*16 = 1024 (i, jt). 256 thr = 8 warps, warp-per-b over 8 b-iters.
// ---------------------------------------------------------------------------
__global__ __launch_bounds__(256, 5) void score_kernel(
        const float* __restrict__ b1, const float* __restrict__ W2,
        const float* __restrict__ b2, float* __restrict__ out) {
    const int i  = blockIdx.x >> 4;
    const int jt = blockIdx.x & 15;

    __shared__ __align__(16) float ce_s[JT][HC];
    __shared__ __align__(16) float w2s[HC];
    __shared__ float red[8][JT];

    const int tid  = threadIdx.x;
    const int warp = tid >> 5;
    const int lane = tid & 31;

    const float* cause  = g_pre;
    const float* effect = g_pre + BC * HC;
    const float* ctx    = g_pre + 2 * BC * HC;

    if (tid < 32) red[tid >> 2][tid & 3] = 0.0f;

    {
        const float4* c4 = reinterpret_cast<const float4*>(cause + i * HC);
        const float4* b4 = reinterpret_cast<const float4*>(b1);
        for (int t = tid; t < JT * HC / 4; t += 256) {
            int j = t >> 8, v = t & 255;
            float4 e4 = reinterpret_cast<const float4*>(effect + (jt * JT + j) * HC)[v];
            float4 cc = c4[v], bb = b4[v];
            float4 rr;
            rr.x = cc.x + e4.x + bb.x;
            rr.y = cc.y + e4.y + bb.y;
            rr.z = cc.z + e4.z + bb.z;
            rr.w = cc.w + e4.w + bb.w;
            reinterpret_cast<float4*>(ce_s[j])[v] = rr;
        }
        for (int t = tid; t < HC / 4; t += 256)
            reinterpret_cast<float4*>(w2s)[t] = reinterpret_cast<const float4*>(W2)[t];
    }
    __syncthreads();

    const unsigned long long C1p = pk2(C1F, C1F);
    const unsigned long long C3p = pk2(C3F, C3F);
    const unsigned long long H2p = pk2(0.5f, 0.5f);
    const float bias2 = b2[0];

    for (int bi = 0; bi < 8; ++bi) {
        const int b = bi * 8 + warp;
        const ulonglong2* ctx2 = reinterpret_cast<const ulonglong2*>(ctx + (size_t)b * HC);
        const ulonglong2* w22  = reinterpret_cast<const ulonglong2*>(w2s);

        unsigned long long acc2[JT];
#pragma unroll
        for (int j = 0; j < JT; ++j) acc2[j] = 0ull;

#pragma unroll 2
        for (int v = lane; v < HC / 4; v += 32) {
            const ulonglong2 x2 = ctx2[v];
            const ulonglong2 wv = w22[v];
#pragma unroll
            for (int j = 0; j < JT; ++j) {
                const ulonglong2 c2 = reinterpret_cast<const ulonglong2*>(ce_s[j])[v];
                GELU_ACC(x2.x, c2.x, wv.x, acc2[j]);
                GELU_ACC(x2.y, c2.y, wv.y, acc2[j]);
            }
        }

        float acc[JT];
#pragma unroll
        for (int j = 0; j < JT; ++j) {
            float lo, hi; upk2(acc2[j], lo, hi);
            acc[j] = lo + hi;
        }
#pragma unroll
        for (int off = 16; off; off >>= 1)
#pragma unroll
            for (int j = 0; j < JT; ++j)
                acc[j] += __shfl_xor_sync(0xffffffffu, acc[j], off);

        if (lane == 0) {
#pragma unroll
            for (int j = 0; j < JT; ++j) {
                float logit = acc[j] + bias2;
                float en = ex2_approx(-1.44269504f * logit);
                red[warp][j] += rcp_approx(1.0f + en);
            }
        }
    }

    __syncthreads();
    if (tid < JT) {
        float s = 0.0f;
#pragma unroll
        for (int w = 0; w < 8; ++w) s += red[w][tid];
        out[i * VC + jt * JT + tid] = s * (1.0f / BC);
    }
}

// ---------------------------------------------------------------------------
extern "C" void kernel_launch(void* const* d_in, const int* in_sizes, int n_in,
                              void* d_out, int out_size) {
    const float* state  = (const float*)d_in[0];
    const float* action = (const float*)d_in[1];
    const float* embed  = (const float*)d_in[2];
    const float* W1     = (const float*)d_in[3];
    const float* b1     = (const float*)d_in[4];
    const float* W2     = (const float*)d_in[5];
    const float* b2     = (const float*)d_in[6];
    float* out          = (float*)d_out;

    gemm_pre_kernel<<<3 * 32 * 4 * KSPLIT, 128>>>(state, action, embed, W1);
    reduce_pre_kernel<<<96, 512>>>();
    score_kernel<<<VC * 16, 256>>>(b1, W2, b2, out);
}

// round 17
// speedup vs baseline: 1.0442x; 1.0376x over previous
#include <cuda_runtime.h>
#include <math.h>

#define DIMC 512
#define HC   1024
#define BC   64
#define VC   64
#define JT   4
#define KSPLIT 4
#define PRE_N (3 * BC * HC)

__device__ __align__(16) float g_pre[PRE_N];
__device__ __align__(16) float g_pre4[KSPLIT][PRE_N];   // K-quarter partials

__device__ __forceinline__ float ex2_approx(float x) {
    float y; asm("ex2.approx.f32 %0, %1;" : "=f"(y) : "f"(x)); return y;
}
__device__ __forceinline__ float rcp_approx(float x) {
    float y; asm("rcp.approx.f32 %0, %1;" : "=f"(y) : "f"(x)); return y;
}
__device__ __forceinline__ float tanh_approx(float x) {
    float y; asm("tanh.approx.f32 %0, %1;" : "=f"(y) : "f"(x)); return y;
}
__device__ __forceinline__ unsigned long long pk2(float lo, float hi) {
    unsigned long long r; asm("mov.b64 %0, {%1,%2};" : "=l"(r) : "f"(lo), "f"(hi)); return r;
}
__device__ __forceinline__ void upk2(unsigned long long v, float& lo, float& hi) {
    asm("mov.b64 {%0,%1}, %2;" : "=f"(lo), "=f"(hi) : "l"(v));
}
__device__ __forceinline__ unsigned long long add2(unsigned long long a, unsigned long long b) {
    unsigned long long r; asm("add.rn.f32x2 %0, %1, %2;" : "=l"(r) : "l"(a), "l"(b)); return r;
}
__device__ __forceinline__ unsigned long long mul2(unsigned long long a, unsigned long long b) {
    unsigned long long r; asm("mul.rn.f32x2 %0, %1, %2;" : "=l"(r) : "l"(a), "l"(b)); return r;
}
__device__ __forceinline__ unsigned long long fma2(unsigned long long a, unsigned long long b, unsigned long long c) {
    unsigned long long r; asm("fma.rn.f32x2 %0, %1, %2, %3;" : "=l"(r) : "l"(a), "l"(b), "l"(c)); return r;
}

// Hendrycks tanh-form GELU: gelu(t) = 0.5*t*(1 + tanh(t*(C1 + C3*t^2)))
#define C1F (0.7978845608f)
#define C3F (0.0356774081f)

// one packed pair of evals accumulated into accr
#define GELU_ACC(xp, cp, wp, accr) do {                                  \
    unsigned long long t2 = add2((xp), (cp));                            \
    unsigned long long s2 = mul2(t2, t2);                                \
    unsigned long long q2 = fma2(s2, C3p, C1p);                          \
    unsigned long long u2 = mul2(q2, t2);                                \
    float ul, uh; upk2(u2, ul, uh);                                      \
    float thl = tanh_approx(ul);                                         \
    float thh = tanh_approx(uh);                                         \
    unsigned long long th2 = pk2(thl, thh);                              \
    unsigned long long hx2 = mul2(t2, H2p);                              \
    unsigned long long g2  = fma2(hx2, th2, hx2);                        \
    (accr) = fma2((wp), g2, (accr));                                     \
} while (0)

// ---------------------------------------------------------------------------
// Kernel 1: pre-activation K-quarter partials, direct store (no atomics).
// grid = 3m x 32ct x 2rt x 4ks = 768 blocks, 128 thr.
// Block = 32 rows x 32 cols x K=128. Thread = 2 rows x 4 cols (8 acc):
// per k-step 2 scalar LDS + 1 LDS.128 feed 8 FMAs (higher LDS intensity).
// ---------------------------------------------------------------------------
__global__ __launch_bounds__(128) void gemm_pre_kernel(
        const float* __restrict__ state, const float* __restrict__ action,
        const float* __restrict__ embed, const float* __restrict__ W1) {
    const int ks  = blockIdx.x & 3;
    const int rt  = (blockIdx.x >> 2) & 1;
    const int b2i = blockIdx.x >> 3;          // 0..95
    const int m   = b2i >> 5;                 // 0..2
    const int ct  = b2i & 31;                 // cols ct*32
    const int tid = threadIdx.x;              // 128

    __shared__ float As[32][33];
    __shared__ __align__(16) float Ws[32][36];

    const int r  = tid & 15;                  // rows r and r+16
    const int cg = tid >> 4;                  // 0..7 -> cols cg*4..+4

    const int rbase = rt * 32;
    const int kbase = ks * 128;
    const int cbase = ct * 32;

    float acc[8];
#pragma unroll
    for (int i = 0; i < 8; ++i) acc[i] = 0.0f;

    const float* Wbase = W1 + (size_t)(m * DIMC + kbase) * HC + cbase;

    float a_pref[8];
    float w_pref[8];

#pragma unroll
    for (int i = 0; i < 8; ++i) {             // 32 rows x 32 k = 1024
        int idx = tid + i * 128;
        int rr = idx >> 5, kk = idx & 31;
        int grow = rbase + rr, gk = kbase + kk;
        if (m == 2) a_pref[i] = state[grow * DIMC + gk] + action[grow * DIMC + gk];
        else        a_pref[i] = embed[grow * DIMC + gk];
    }
#pragma unroll
    for (int i = 0; i < 8; ++i) {             // 32 k x 32 cols = 1024
        int idx = tid + i * 128;
        int kk = idx >> 5, cc = idx & 31;
        w_pref[i] = Wbase[(size_t)kk * HC + cc];
    }

    for (int ch = 0; ch < 4; ++ch) {          // 4 chunks of 32 k
        __syncthreads();
#pragma unroll
        for (int i = 0; i < 8; ++i) {
            int idx = tid + i * 128;
            As[idx >> 5][idx & 31] = a_pref[i];
        }
#pragma unroll
        for (int i = 0; i < 8; ++i) {
            int idx = tid + i * 128;
            Ws[idx >> 5][idx & 31] = w_pref[i];
        }
        __syncthreads();

        if (ch < 3) {
            const int k0 = kbase + (ch + 1) * 32;
#pragma unroll
            for (int i = 0; i < 8; ++i) {
                int idx = tid + i * 128;
                int rr = idx >> 5, kk = idx & 31;
                int grow = rbase + rr, gk = k0 + kk;
                if (m == 2) a_pref[i] = state[grow * DIMC + gk] + action[grow * DIMC + gk];
                else        a_pref[i] = embed[grow * DIMC + gk];
            }
#pragma unroll
            for (int i = 0; i < 8; ++i) {
                int idx = tid + i * 128;
                int kk = idx >> 5, cc = idx & 31;
                w_pref[i] = Wbase[(size_t)((ch + 1) * 32 + kk) * HC + cc];
            }
        }

#pragma unroll
        for (int k = 0; k < 32; ++k) {
            float a0 = As[r][k];
            float a1 = As[r + 16][k];
            float4 w4 = *reinterpret_cast<const float4*>(&Ws[k][cg * 4]);
            acc[0] = fmaf(a0, w4.x, acc[0]);
            acc[1] = fmaf(a0, w4.y, acc[1]);
            acc[2] = fmaf(a0, w4.z, acc[2]);
            acc[3] = fmaf(a0, w4.w, acc[3]);
            acc[4] = fmaf(a1, w4.x, acc[4]);
            acc[5] = fmaf(a1, w4.y, acc[5]);
            acc[6] = fmaf(a1, w4.z, acc[6]);
            acc[7] = fmaf(a1, w4.w, acc[7]);
        }
    }

    float* out0 = g_pre4[ks] + (size_t)(m * BC + rbase + r) * HC + cbase + cg * 4;
    float* out1 = g_pre4[ks] + (size_t)(m * BC + rbase + r + 16) * HC + cbase + cg * 4;
    *reinterpret_cast<float4*>(out0) = make_float4(acc[0], acc[1], acc[2], acc[3]);
    *reinterpret_cast<float4*>(out1) = make_float4(acc[4], acc[5], acc[6], acc[7]);
}

// ---------------------------------------------------------------------------
// Kernel 1b: reduce 4 K-quarter partials (fixed order -> deterministic).
// 49152 float4; grid 96 x 512.
// ---------------------------------------------------------------------------
__global__ __launch_bounds__(512) void reduce_pre_kernel() {
    int idx = blockIdx.x * 512 + threadIdx.x;      // 0..49151
    const float4* p0 = reinterpret_cast<const float4*>(g_pre4[0]);
    const float4* p1 = reinterpret_cast<const float4*>(g_pre4[1]);
    const float4* p2 = reinterpret_cast<const float4*>(g_pre4[2]);
    const float4* p3 = reinterpret_cast<const float4*>(g_pre4[3]);
    float4 a = p0[idx], b = p1[idx], c = p2[idx], d = p3[idx];
    float4 r;
    r.x = (a.x + b.x) + (c.x + d.x);
    r.y = (a.y + b.y) + (c.y + d.y);
    r.z = (a.z + b.z) + (c.z + d.z);
    r.w = (a.w + b.w) + (c.w + d.w);
    reinterpret_cast<float4*>(g_pre)[idx] = r;
}

// ---------------------------------------------------------------------------
// Kernel 2: scores (round-13 proven config, untouched).
// grid = 64*16 = 1024 (i, jt). 256 thr = 8 warps, warp-per-b over 8 b-iters.
// ---------------------------------------------------------------------------
__global__ __launch_bounds__(256, 5) void score_kernel(
        const float* __restrict__ b1, const float* __restrict__ W2,
        const float* __restrict__ b2, float* __restrict__ out) {
    const int i  = blockIdx.x >> 4;
    const int jt = blockIdx.x & 15;

    __shared__ __align__(16) float ce_s[JT][HC];
    __shared__ __align__(16) float w2s[HC];
    __shared__ float red[8][JT];

    const int tid  = threadIdx.x;
    const int warp = tid >> 5;
    const int lane = tid & 31;

    const float* cause  = g_pre;
    const float* effect = g_pre + BC * HC;
    const float* ctx    = g_pre + 2 * BC * HC;

    if (tid < 32) red[tid >> 2][tid & 3] = 0.0f;

    {
        const float4* c4 = reinterpret_cast<const float4*>(cause + i * HC);
        const float4* b4 = reinterpret_cast<const float4*>(b1);
        for (int t = tid; t < JT * HC / 4; t += 256) {
            int j = t >> 8, v = t & 255;
            float4 e4 = reinterpret_cast<const float4*>(effect + (jt * JT + j) * HC)[v];
            float4 cc = c4[v], bb = b4[v];
            float4 rr;
            rr.x = cc.x + e4.x + bb.x;
            rr.y = cc.y + e4.y + bb.y;
            rr.z = cc.z + e4.z + bb.z;
            rr.w = cc.w + e4.w + bb.w;
            reinterpret_cast<float4*>(ce_s[j])[v] = rr;
        }
        for (int t = tid; t < HC / 4; t += 256)
            reinterpret_cast<float4*>(w2s)[t] = reinterpret_cast<const float4*>(W2)[t];
    }
    __syncthreads();

    const unsigned long long C1p = pk2(C1F, C1F);
    const unsigned long long C3p = pk2(C3F, C3F);
    const unsigned long long H2p = pk2(0.5f, 0.5f);
    const float bias2 = b2[0];

    for (int bi = 0; bi < 8; ++bi) {
        const int b = bi * 8 + warp;
        const ulonglong2* ctx2 = reinterpret_cast<const ulonglong2*>(ctx + (size_t)b * HC);
        const ulonglong2* w22  = reinterpret_cast<const ulonglong2*>(w2s);

        unsigned long long acc2[JT];
#pragma unroll
        for (int j = 0; j < JT; ++j) acc2[j] = 0ull;

#pragma unroll 2
        for (int v = lane; v < HC / 4; v += 32) {
            const ulonglong2 x2 = ctx2[v];
            const ulonglong2 wv = w22[v];
#pragma unroll
            for (int j = 0; j < JT; ++j) {
                const ulonglong2 c2 = reinterpret_cast<const ulonglong2*>(ce_s[j])[v];
                GELU_ACC(x2.x, c2.x, wv.x, acc2[j]);
                GELU_ACC(x2.y, c2.y, wv.y, acc2[j]);
            }
        }

        float acc[JT];
#pragma unroll
        for (int j = 0; j < JT; ++j) {
            float lo, hi; upk2(acc2[j], lo, hi);
            acc[j] = lo + hi;
        }
#pragma unroll
        for (int off = 16; off; off >>= 1)
#pragma unroll
            for (int j = 0; j < JT; ++j)
                acc[j] += __shfl_xor_sync(0xffffffffu, acc[j], off);

        if (lane == 0) {
#pragma unroll
            for (int j = 0; j < JT; ++j) {
                float logit = acc[j] + bias2;
                float en = ex2_approx(-1.44269504f * logit);
                red[warp][j] += rcp_approx(1.0f + en);
            }
        }
    }

    __syncthreads();
    if (tid < JT) {
        float s = 0.0f;
#pragma unroll
        for (int w = 0; w < 8; ++w) s += red[w][tid];
        out[i * VC + jt * JT + tid] = s * (1.0f / BC);
    }
}

// ---------------------------------------------------------------------------
extern "C" void kernel_launch(void* const* d_in, const int* in_sizes, int n_in,
                              void* d_out, int out_size) {
    const float* state  = (const float*)d_in[0];
    const float* action = (const float*)d_in[1];
    const float* embed  = (const float*)d_in[2];
    const float* W1     = (const float*)d_in[3];
    const float* b1     = (const float*)d_in[4];
    const float* W2     = (const float*)d_in[5];
    const float* b2     = (const float*)d_in[6];
    float* out          = (float*)d_out;

    gemm_pre_kernel<<<3 * 32 * 2 * KSPLIT, 128>>>(state, action, embed, W1);
    reduce_pre_kernel<<<96, 512>>>();
    score_kernel<<<VC * 16, 256>>>(b1, W2, b2, out);
}